// round 4
// baseline (speedup 1.0000x reference)
#include <cuda_runtime.h>
#include <math.h>

#define BATCH 4
#define CDIM  256
#define HW    4096

// ---------------- scratch (no allocations allowed) ----------------
static __device__ float g_P[(size_t)BATCH * HW * HW];          // 268 MB: logits / probs
static __device__ float g_ax[(size_t)BATCH * HW * CDIM];
static __device__ float g_ux[(size_t)BATCH * HW * CDIM];
static __device__ float g_gen[(size_t)BATCH * HW * CDIM];      // gen, n-major (b,hw,c)
static __device__ float g_gencn[(size_t)BATCH * HW * CDIM];    // gen, c-major (b,c,hw)
static __device__ float g_sktnc[(size_t)BATCH * HW * CDIM];
static __device__ float g_refnc[(size_t)BATCH * HW * CDIM];
static __device__ float g_colpart[(size_t)BATCH * 16 * HW];
static __device__ float g_colinv[(size_t)BATCH * HW];

// ---------------- tf32 helpers ----------------
__device__ __forceinline__ unsigned f2tf(float x) {
    unsigned r;
    asm("cvt.rna.tf32.f32 %0, %1;" : "=r"(r) : "f"(x));
    return r;
}

__device__ __forceinline__ void mma_tf32(float* d, const unsigned* a, const unsigned* b) {
    asm("mma.sync.aligned.m16n8k8.row.col.f32.tf32.tf32.f32 "
        "{%0,%1,%2,%3},{%4,%5,%6,%7},{%8,%9},{%0,%1,%2,%3};"
        : "+f"(d[0]), "+f"(d[1]), "+f"(d[2]), "+f"(d[3])
        : "r"(a[0]), "r"(a[1]), "r"(a[2]), "r"(a[3]), "r"(b[0]), "r"(b[1]));
}

// ---------------- transpose: in (b,R,S) -> out (b,S,R) ----------------
__global__ void transpose_kernel(const float* __restrict__ in, float* __restrict__ out,
                                 int R, int S) {
    __shared__ float tile[32][33];
    int b = blockIdx.z;
    int s0 = blockIdx.x * 32, r0 = blockIdx.y * 32;
    const float* inb = in + (size_t)b * R * S;
    float* outb = out + (size_t)b * R * S;
    int tx = threadIdx.x, ty = threadIdx.y;
#pragma unroll
    for (int i = 0; i < 32; i += 8)
        tile[ty + i][tx] = inb[(size_t)(r0 + ty + i) * S + s0 + tx];
    __syncthreads();
#pragma unroll
    for (int i = 0; i < 32; i += 8)
        outb[(size_t)(s0 + ty + i) * R + r0 + tx] = tile[tx][ty + i];
}

// =====================================================================
// gemm_rr: C[m][n] = sum_k A[m][k] * B[k][n]   (A row-major, B row-major)
//   N fixed = CDIM = 256 (ldb = ldc = 256). K, lda are parameters.
//   EPI==1: out = relu(C + bias[n])
//   EPI==2: out = C + U + R
//   THREE : 3xTF32 split for near-fp32 accuracy.
// CTA tile 128x128, 8 warps (2m x 4n), warp tile 64x32, BK=32.
// =====================================================================
template<bool THREE, int EPI>
__global__ __launch_bounds__(256, 2)
void gemm_rr(const float* __restrict__ A, const float* __restrict__ B,
             const float* __restrict__ bias,
             const float* __restrict__ U, const float* __restrict__ Rr,
             float* __restrict__ C,
             int K, int lda, size_t sA, size_t sB, size_t sC) {
    extern __shared__ unsigned sm[];
    // As[128][36], (Asr), Bs[32][136], (Bsr)
    unsigned* As  = sm;
    unsigned* Asr = As + 128 * 36;                   // valid only if THREE
    unsigned* Bs  = As + (THREE ? 2 : 1) * 128 * 36;
    unsigned* Bsr = Bs + 32 * 136;

    int b = blockIdx.z;
    const float* Ab = A + (size_t)b * sA;
    const float* Bb = B + (size_t)b * sB;
    int n0 = blockIdx.x * 128;
    int m0 = blockIdx.y * 128;
    int tid = threadIdx.x;
    int warp = tid >> 5, lane = tid & 31;
    int g = lane >> 2, t = lane & 3;
    int wm = warp >> 2, wn = warp & 3;   // 2 x 4
    int la_n = tid >> 3, la_k = (tid & 7) * 4;
    int lb_k = tid >> 5, lb_n = (tid & 31) * 4;

    float acc[4][4][4] = {};

    for (int k0 = 0; k0 < K; k0 += 32) {
        // ---- stage A tile 128x32 ----
#pragma unroll
        for (int u = 0; u < 4; u++) {
            int n = la_n + u * 32;
            float4 v = *(const float4*)&Ab[(size_t)(m0 + n) * lda + k0 + la_k];
            unsigned h0 = f2tf(v.x), h1 = f2tf(v.y), h2 = f2tf(v.z), h3 = f2tf(v.w);
            unsigned* p = &As[n * 36 + la_k];
            p[0] = h0; p[1] = h1; p[2] = h2; p[3] = h3;
            if (THREE) {
                unsigned* q = &Asr[n * 36 + la_k];
                q[0] = f2tf(v.x - __uint_as_float(h0));
                q[1] = f2tf(v.y - __uint_as_float(h1));
                q[2] = f2tf(v.z - __uint_as_float(h2));
                q[3] = f2tf(v.w - __uint_as_float(h3));
            }
        }
        // ---- stage B tile 32x128 ----
#pragma unroll
        for (int u = 0; u < 4; u++) {
            int k = lb_k + u * 8;
            float4 v = *(const float4*)&Bb[(size_t)(k0 + k) * CDIM + n0 + lb_n];
            unsigned h0 = f2tf(v.x), h1 = f2tf(v.y), h2 = f2tf(v.z), h3 = f2tf(v.w);
            unsigned* p = &Bs[k * 136 + lb_n];
            p[0] = h0; p[1] = h1; p[2] = h2; p[3] = h3;
            if (THREE) {
                unsigned* q = &Bsr[k * 136 + lb_n];
                q[0] = f2tf(v.x - __uint_as_float(h0));
                q[1] = f2tf(v.y - __uint_as_float(h1));
                q[2] = f2tf(v.z - __uint_as_float(h2));
                q[3] = f2tf(v.w - __uint_as_float(h3));
            }
        }
        __syncthreads();

#pragma unroll
        for (int c = 0; c < 4; c++) {
            int kc = c * 8;
            unsigned bb[4][2], br[4][2];
#pragma unroll
            for (int j = 0; j < 4; j++) {
                int col = wn * 32 + j * 8 + g;
                bb[j][0] = Bs[(kc + t) * 136 + col];
                bb[j][1] = Bs[(kc + t + 4) * 136 + col];
                if (THREE) {
                    br[j][0] = Bsr[(kc + t) * 136 + col];
                    br[j][1] = Bsr[(kc + t + 4) * 136 + col];
                }
            }
#pragma unroll
            for (int i = 0; i < 4; i++) {
                int row = wm * 64 + i * 16 + g;
                unsigned aa[4], ar[4];
                aa[0] = As[row * 36 + kc + t];
                aa[1] = As[(row + 8) * 36 + kc + t];
                aa[2] = As[row * 36 + kc + t + 4];
                aa[3] = As[(row + 8) * 36 + kc + t + 4];
                if (THREE) {
                    ar[0] = Asr[row * 36 + kc + t];
                    ar[1] = Asr[(row + 8) * 36 + kc + t];
                    ar[2] = Asr[row * 36 + kc + t + 4];
                    ar[3] = Asr[(row + 8) * 36 + kc + t + 4];
                }
#pragma unroll
                for (int j = 0; j < 4; j++) {
                    mma_tf32(acc[i][j], aa, bb[j]);
                    if (THREE) {
                        mma_tf32(acc[i][j], aa, br[j]);
                        mma_tf32(acc[i][j], ar, bb[j]);
                    }
                }
            }
        }
        __syncthreads();
    }

    // ---- epilogue ----
    float* Cb = C + (size_t)b * sC;
#pragma unroll
    for (int i = 0; i < 4; i++) {
        int r = m0 + wm * 64 + i * 16 + g;
#pragma unroll
        for (int j = 0; j < 4; j++) {
            int cc = n0 + wn * 32 + j * 8 + 2 * t;
            size_t o0 = (size_t)r * CDIM + cc;
            size_t o1 = (size_t)(r + 8) * CDIM + cc;
            if (EPI == 1) {
                float2 bv = *(const float2*)&bias[cc];
                float2 v0 = make_float2(fmaxf(acc[i][j][0] + bv.x, 0.f),
                                        fmaxf(acc[i][j][1] + bv.y, 0.f));
                float2 v1 = make_float2(fmaxf(acc[i][j][2] + bv.x, 0.f),
                                        fmaxf(acc[i][j][3] + bv.y, 0.f));
                *(float2*)&Cb[o0] = v0;
                *(float2*)&Cb[o1] = v1;
            } else {
                const float* Ub = U + (size_t)b * sC;
                const float* Rb = Rr + (size_t)b * sC;
                float2 u0 = *(const float2*)&Ub[o0], u1 = *(const float2*)&Ub[o1];
                float2 q0 = *(const float2*)&Rb[o0], q1 = *(const float2*)&Rb[o1];
                float2 v0 = make_float2(acc[i][j][0] + u0.x + q0.x,
                                        acc[i][j][1] + u0.y + q0.y);
                float2 v1 = make_float2(acc[i][j][2] + u1.x + q1.x,
                                        acc[i][j][3] + u1.y + q1.y);
                *(float2*)&Cb[o0] = v0;
                *(float2*)&Cb[o1] = v1;
            }
        }
    }
}

// =====================================================================
// logits_mma: L[n][m] = sum_k A[k][n] * B[k][m]  (A,B c-major (CDIM,HW))
// Always 3xTF32. CTA tile 128x128, K = CDIM = 256.
// =====================================================================
__global__ __launch_bounds__(256, 2)
void logits_mma(const float* __restrict__ A, const float* __restrict__ B,
                float* __restrict__ L) {
    extern __shared__ unsigned sm[];
    unsigned* As  = sm;                 // [32][136]
    unsigned* Asr = As + 32 * 136;
    unsigned* Bs  = Asr + 32 * 136;
    unsigned* Bsr = Bs + 32 * 136;

    int b = blockIdx.z;
    const float* Ab = A + (size_t)b * CDIM * HW;
    const float* Bb = B + (size_t)b * CDIM * HW;
    float* Lb = L + (size_t)b * HW * HW;
    int m0 = blockIdx.x * 128;   // cols of L
    int n0 = blockIdx.y * 128;   // rows of L
    int tid = threadIdx.x;
    int warp = tid >> 5, lane = tid & 31;
    int g = lane >> 2, t = lane & 3;
    int wm = warp >> 2, wn = warp & 3;
    int l_k = tid >> 5, l_n = (tid & 31) * 4;

    float acc[4][4][4] = {};

    for (int k0 = 0; k0 < CDIM; k0 += 32) {
#pragma unroll
        for (int u = 0; u < 4; u++) {
            int k = l_k + u * 8;
            {
                float4 v = *(const float4*)&Ab[(size_t)(k0 + k) * HW + n0 + l_n];
                unsigned h0 = f2tf(v.x), h1 = f2tf(v.y), h2 = f2tf(v.z), h3 = f2tf(v.w);
                unsigned* p = &As[k * 136 + l_n];
                p[0] = h0; p[1] = h1; p[2] = h2; p[3] = h3;
                unsigned* q = &Asr[k * 136 + l_n];
                q[0] = f2tf(v.x - __uint_as_float(h0));
                q[1] = f2tf(v.y - __uint_as_float(h1));
                q[2] = f2tf(v.z - __uint_as_float(h2));
                q[3] = f2tf(v.w - __uint_as_float(h3));
            }
            {
                float4 v = *(const float4*)&Bb[(size_t)(k0 + k) * HW + m0 + l_n];
                unsigned h0 = f2tf(v.x), h1 = f2tf(v.y), h2 = f2tf(v.z), h3 = f2tf(v.w);
                unsigned* p = &Bs[k * 136 + l_n];
                p[0] = h0; p[1] = h1; p[2] = h2; p[3] = h3;
                unsigned* q = &Bsr[k * 136 + l_n];
                q[0] = f2tf(v.x - __uint_as_float(h0));
                q[1] = f2tf(v.y - __uint_as_float(h1));
                q[2] = f2tf(v.z - __uint_as_float(h2));
                q[3] = f2tf(v.w - __uint_as_float(h3));
            }
        }
        __syncthreads();

#pragma unroll
        for (int c = 0; c < 4; c++) {
            int kc = c * 8;
            unsigned bb[4][2], br[4][2];
#pragma unroll
            for (int j = 0; j < 4; j++) {
                int col = wn * 32 + j * 8 + g;
                bb[j][0] = Bs[(kc + t) * 136 + col];
                bb[j][1] = Bs[(kc + t + 4) * 136 + col];
                br[j][0] = Bsr[(kc + t) * 136 + col];
                br[j][1] = Bsr[(kc + t + 4) * 136 + col];
            }
#pragma unroll
            for (int i = 0; i < 4; i++) {
                int row = wm * 64 + i * 16 + g;
                unsigned aa[4], ar[4];
                aa[0] = As[(kc + t) * 136 + row];
                aa[1] = As[(kc + t) * 136 + row + 8];
                aa[2] = As[(kc + t + 4) * 136 + row];
                aa[3] = As[(kc + t + 4) * 136 + row + 8];
                ar[0] = Asr[(kc + t) * 136 + row];
                ar[1] = Asr[(kc + t) * 136 + row + 8];
                ar[2] = Asr[(kc + t + 4) * 136 + row];
                ar[3] = Asr[(kc + t + 4) * 136 + row + 8];
#pragma unroll
                for (int j = 0; j < 4; j++) {
                    mma_tf32(acc[i][j], aa, bb[j]);
                    mma_tf32(acc[i][j], aa, br[j]);
                    mma_tf32(acc[i][j], ar, bb[j]);
                }
            }
        }
        __syncthreads();
    }

#pragma unroll
    for (int i = 0; i < 4; i++) {
        int r = n0 + wm * 64 + i * 16 + g;
#pragma unroll
        for (int j = 0; j < 4; j++) {
            int cc = m0 + wn * 32 + j * 8 + 2 * t;
            *(float2*)&Lb[(size_t)r * HW + cc] =
                make_float2(acc[i][j][0], acc[i][j][1]);
            *(float2*)&Lb[(size_t)(r + 8) * HW + cc] =
                make_float2(acc[i][j][2], acc[i][j][3]);
        }
    }
}

// ---------------- row softmax in place (row length HW, block 512) ----------------
__global__ void softmax_kernel(float* __restrict__ P) {
    float* row = P + ((size_t)blockIdx.y * HW + blockIdx.x) * HW;
    int t = threadIdx.x;
    __shared__ float red[16];
    float v[8];
    float mx = -1e30f;
#pragma unroll
    for (int i = 0; i < 8; i++) { v[i] = row[t + i * 512]; mx = fmaxf(mx, v[i]); }
    for (int o = 16; o; o >>= 1) mx = fmaxf(mx, __shfl_xor_sync(0xffffffffu, mx, o));
    int warp = t >> 5, lane = t & 31;
    if (lane == 0) red[warp] = mx;
    __syncthreads();
    if (warp == 0) {
        float m2 = red[lane & 15];
        for (int o = 8; o; o >>= 1) m2 = fmaxf(m2, __shfl_xor_sync(0xffffffffu, m2, o));
        if (lane == 0) red[0] = m2;
    }
    __syncthreads();
    mx = red[0];
    __syncthreads();
    float s = 0.f;
#pragma unroll
    for (int i = 0; i < 8; i++) { v[i] = __expf(v[i] - mx); s += v[i]; }
    for (int o = 16; o; o >>= 1) s += __shfl_xor_sync(0xffffffffu, s, o);
    if (lane == 0) red[warp] = s;
    __syncthreads();
    if (warp == 0) {
        float s2 = red[lane & 15];
        for (int o = 8; o; o >>= 1) s2 += __shfl_xor_sync(0xffffffffu, s2, o);
        if (lane == 0) red[0] = s2;
    }
    __syncthreads();
    float inv = 1.f / red[0];
#pragma unroll
    for (int i = 0; i < 8; i++) row[t + i * 512] = v[i] * inv;
}

// ---------------- column partial sums ----------------
__global__ void colsum_kernel(const float* __restrict__ P, float* __restrict__ part) {
    int b = blockIdx.z;
    int m = blockIdx.x * 256 + threadIdx.x;
    int r0 = blockIdx.y * 256;
    const float* Pb = P + (size_t)b * HW * HW;
    float s = 0.f;
#pragma unroll 8
    for (int r = 0; r < 256; r++) s += Pb[(size_t)(r0 + r) * HW + m];
    part[((size_t)b * 16 + blockIdx.y) * HW + m] = s;
}

__global__ void colinv_kernel(const float* __restrict__ part, float* __restrict__ colinv) {
    int i = blockIdx.x * 256 + threadIdx.x;
    int b = i >> 12, m = i & (HW - 1);
    float s = 0.f;
#pragma unroll
    for (int c2 = 0; c2 < 16; c2++) s += part[((size_t)b * 16 + c2) * HW + m];
    colinv[i] = 1.f / fmaxf(s, 1e-12f);
}

__global__ void scale_ax_kernel(float* __restrict__ ax, const float* __restrict__ colinv) {
    size_t f4 = (size_t)blockIdx.x * 256 + threadIdx.x;
    int row = (int)(f4 >> 6);
    float sc = colinv[row];
    float4 v = ((float4*)ax)[f4];
    v.x *= sc; v.y *= sc; v.z *= sc; v.w *= sc;
    ((float4*)ax)[f4] = v;
}

// ---------------- launch ----------------
extern "C" void kernel_launch(void* const* d_in, const int* in_sizes, int n_in,
                              void* d_out, int out_size) {
    (void)in_sizes; (void)n_in; (void)out_size;
    const float* skt = (const float*)d_in[0];
    const float* ref = (const float*)d_in[1];
    const float* Wa3 = (const float*)d_in[2];
    const float* ba3 = (const float*)d_in[3];
    const float* Wu3 = (const float*)d_in[4];
    const float* bu3 = (const float*)d_in[5];
    const float* Wa4 = (const float*)d_in[6];
    const float* ba4 = (const float*)d_in[7];
    const float* Wu4 = (const float*)d_in[8];
    const float* bu4 = (const float*)d_in[9];
    float* out = (float*)d_out;

    float *P, *ax, *ux, *gen, *gencn, *sktnc, *refnc, *colpart, *colinv;
    cudaGetSymbolAddress((void**)&P, g_P);
    cudaGetSymbolAddress((void**)&ax, g_ax);
    cudaGetSymbolAddress((void**)&ux, g_ux);
    cudaGetSymbolAddress((void**)&gen, g_gen);
    cudaGetSymbolAddress((void**)&gencn, g_gencn);
    cudaGetSymbolAddress((void**)&sktnc, g_sktnc);
    cudaGetSymbolAddress((void**)&refnc, g_refnc);
    cudaGetSymbolAddress((void**)&colpart, g_colpart);
    cudaGetSymbolAddress((void**)&colinv, g_colinv);

    const int SM3 = (2 * 128 * 36 + 2 * 32 * 136) * 4;   // 71680
    const int SM1 = (128 * 36 + 32 * 136) * 4;           // 35840
    const int SML = 4 * 32 * 136 * 4;                    // 69632
    cudaFuncSetAttribute(gemm_rr<true, 1>,  cudaFuncAttributeMaxDynamicSharedMemorySize, SM3);
    cudaFuncSetAttribute(gemm_rr<true, 2>,  cudaFuncAttributeMaxDynamicSharedMemorySize, SM3);
    cudaFuncSetAttribute(gemm_rr<false, 1>, cudaFuncAttributeMaxDynamicSharedMemorySize, SM1);
    cudaFuncSetAttribute(gemm_rr<false, 2>, cudaFuncAttributeMaxDynamicSharedMemorySize, SM1);
    cudaFuncSetAttribute(logits_mma,        cudaFuncAttributeMaxDynamicSharedMemorySize, SML);

    dim3 tb(32, 8);
    dim3 gLin(CDIM / 128, (BATCH * HW) / 128, 1);
    dim3 gLog(HW / 128, HW / 128, BATCH);
    dim3 gPax(CDIM / 128, HW / 128, BATCH);

    // ===== layer 1 (3xTF32 everywhere: errors amplify x~40 through softmax) =====
    transpose_kernel<<<dim3(HW / 32, CDIM / 32, BATCH), tb>>>(skt, sktnc, CDIM, HW);
    transpose_kernel<<<dim3(HW / 32, CDIM / 32, BATCH), tb>>>(ref, refnc, CDIM, HW);
    gemm_rr<true, 1><<<gLin, 256, SM3>>>(refnc, Wa3, ba3, nullptr, nullptr, ax,
                                         CDIM, CDIM, 0, 0, 0);
    gemm_rr<true, 1><<<gLin, 256, SM3>>>(sktnc, Wu3, bu3, nullptr, nullptr, ux,
                                         CDIM, CDIM, 0, 0, 0);
    logits_mma<<<gLog, 256, SML>>>(skt, ref, P);
    softmax_kernel<<<dim3(HW, BATCH), 512>>>(P);
    colsum_kernel<<<dim3(HW / 256, 16, BATCH), 256>>>(P, colpart);
    colinv_kernel<<<(BATCH * HW) / 256, 256>>>(colpart, colinv);
    scale_ax_kernel<<<(BATCH * HW * CDIM) / (4 * 256), 256>>>(ax, colinv);
    gemm_rr<true, 2><<<gPax, 256, SM3>>>(P, ax, nullptr, ux, sktnc, gen,
                                         HW, HW,
                                         (size_t)HW * HW, (size_t)HW * CDIM, (size_t)HW * CDIM);

    // ===== layer 2 (logits still 3x; final linears/pax plain tf32) =====
    transpose_kernel<<<dim3(CDIM / 32, HW / 32, BATCH), tb>>>(gen, gencn, HW, CDIM);
    gemm_rr<false, 1><<<gLin, 256, SM1>>>(gen, Wa4, ba4, nullptr, nullptr, ax,
                                          CDIM, CDIM, 0, 0, 0);
    gemm_rr<false, 1><<<gLin, 256, SM1>>>(gen, Wu4, bu4, nullptr, nullptr, ux,
                                          CDIM, CDIM, 0, 0, 0);
    logits_mma<<<gLog, 256, SML>>>(gencn, gencn, P);
    softmax_kernel<<<dim3(HW, BATCH), 512>>>(P);
    colsum_kernel<<<dim3(HW / 256, 16, BATCH), 256>>>(P, colpart);
    colinv_kernel<<<(BATCH * HW) / 256, 256>>>(colpart, colinv);
    scale_ax_kernel<<<(BATCH * HW * CDIM) / (4 * 256), 256>>>(ax, colinv);
    gemm_rr<false, 2><<<gPax, 256, SM1>>>(P, ax, nullptr, ux, gen, out,
                                          HW, HW,
                                          (size_t)HW * HW, (size_t)HW * CDIM, (size_t)HW * CDIM);
}

// round 5
// speedup vs baseline: 1.0592x; 1.0592x over previous
#include <cuda_runtime.h>
#include <math.h>

#define BATCH 4
#define CDIM  256
#define HW    4096

// ---------------- scratch (no allocations allowed) ----------------
static __device__ float g_P[(size_t)BATCH * HW * HW];          // 268 MB: logits / probs
static __device__ float g_ax[(size_t)BATCH * HW * CDIM];
static __device__ float g_ux[(size_t)BATCH * HW * CDIM];
static __device__ float g_gen[(size_t)BATCH * HW * CDIM];      // gen, n-major (b,hw,c)
static __device__ float g_gencn[(size_t)BATCH * HW * CDIM];    // gen, c-major (b,c,hw)
static __device__ float g_sktnc[(size_t)BATCH * HW * CDIM];
static __device__ float g_refnc[(size_t)BATCH * HW * CDIM];
static __device__ float g_colpart[(size_t)BATCH * 16 * HW];
static __device__ float g_colinv[(size_t)BATCH * HW];
// tf32 hi/lo pre-split operands for logits GEMMs
static __device__ unsigned g_hi0[(size_t)BATCH * HW * CDIM];
static __device__ unsigned g_lo0[(size_t)BATCH * HW * CDIM];
static __device__ unsigned g_hi1[(size_t)BATCH * HW * CDIM];
static __device__ unsigned g_lo1[(size_t)BATCH * HW * CDIM];

// ---------------- tf32 helpers ----------------
__device__ __forceinline__ unsigned f2tf(float x) {
    unsigned r;
    asm("cvt.rna.tf32.f32 %0, %1;" : "=r"(r) : "f"(x));
    return r;
}

__device__ __forceinline__ void mma_tf32(float* d, const unsigned* a, const unsigned* b) {
    asm("mma.sync.aligned.m16n8k8.row.col.f32.tf32.tf32.f32 "
        "{%0,%1,%2,%3},{%4,%5,%6,%7},{%8,%9},{%0,%1,%2,%3};"
        : "+f"(d[0]), "+f"(d[1]), "+f"(d[2]), "+f"(d[3])
        : "r"(a[0]), "r"(a[1]), "r"(a[2]), "r"(a[3]), "r"(b[0]), "r"(b[1]));
}

__device__ __forceinline__ void cpa16(unsigned saddr, const void* g) {
    asm volatile("cp.async.cg.shared.global [%0], [%1], 16;\n" :: "r"(saddr), "l"(g));
}

// ---------------- split: float -> (tf32 hi, tf32 lo) ----------------
__global__ void split_kernel(const float* __restrict__ in, unsigned* __restrict__ hi,
                             unsigned* __restrict__ lo) {
    size_t i = (size_t)blockIdx.x * 256 + threadIdx.x;   // float4 index
    float4 v = ((const float4*)in)[i];
    uint4 h, l;
    h.x = f2tf(v.x); l.x = f2tf(v.x - __uint_as_float(h.x));
    h.y = f2tf(v.y); l.y = f2tf(v.y - __uint_as_float(h.y));
    h.z = f2tf(v.z); l.z = f2tf(v.z - __uint_as_float(h.z));
    h.w = f2tf(v.w); l.w = f2tf(v.w - __uint_as_float(h.w));
    ((uint4*)hi)[i] = h;
    ((uint4*)lo)[i] = l;
}

// ---------------- transpose: in (b,R,S) -> out (b,S,R) ----------------
__global__ void transpose_kernel(const float* __restrict__ in, float* __restrict__ out,
                                 int R, int S) {
    __shared__ float tile[32][33];
    int b = blockIdx.z;
    int s0 = blockIdx.x * 32, r0 = blockIdx.y * 32;
    const float* inb = in + (size_t)b * R * S;
    float* outb = out + (size_t)b * R * S;
    int tx = threadIdx.x, ty = threadIdx.y;
#pragma unroll
    for (int i = 0; i < 32; i += 8)
        tile[ty + i][tx] = inb[(size_t)(r0 + ty + i) * S + s0 + tx];
    __syncthreads();
#pragma unroll
    for (int i = 0; i < 32; i += 8)
        outb[(size_t)(s0 + ty + i) * R + r0 + tx] = tile[tx][ty + i];
}

// =====================================================================
// logits_cp: L[n][m] = sum_k A[k][n] * B[k][m], 3xTF32 from pre-split
// hi/lo operands, cp.async double-buffered. SYM: compute only upper
// triangle of blocks, mirror off-diagonal tiles (L symmetric).
// CTA 128x128, 8 warps 2x4, BK=32, K=CDIM=256.
// =====================================================================
template<bool SYM>
__global__ __launch_bounds__(256)
void logits_cp(const unsigned* __restrict__ Ah, const unsigned* __restrict__ Al,
               const unsigned* __restrict__ Bh, const unsigned* __restrict__ Bl,
               float* __restrict__ L) {
    extern __shared__ unsigned sm[];
    constexpr int ARR = 32 * 136;      // words per array
    constexpr int STG = 4 * ARR;       // words per stage
    constexpr int NIT = CDIM / 32;     // 8

    int bx = blockIdx.x, by = blockIdx.y, b = blockIdx.z;
    if (SYM && bx < by) return;
    int m0 = bx * 128;   // cols of L
    int n0 = by * 128;   // rows of L

    const unsigned* Ahb = Ah + (size_t)b * CDIM * HW;
    const unsigned* Alb = Al + (size_t)b * CDIM * HW;
    const unsigned* Bhb = Bh + (size_t)b * CDIM * HW;
    const unsigned* Blb = Bl + (size_t)b * CDIM * HW;
    float* Lb = L + (size_t)b * HW * HW;

    unsigned sbase;
    asm("{ .reg .u64 t0; cvta.to.shared.u64 t0, %1; cvt.u32.u64 %0, t0; }"
        : "=r"(sbase) : "l"(sm));

    int tid = threadIdx.x;
    int warp = tid >> 5, lane = tid & 31;
    int g = lane >> 2, t = lane & 3;
    int wm = warp >> 2, wn = warp & 3;

    auto prefetch = [&](int it, int s) {
        int k0 = it * 32;
#pragma unroll
        for (int q = 0; q < 4; q++) {
            int f = tid + q * 256;
            int k = f >> 5, c4 = (f & 31) * 4;
            size_t go = (size_t)(k0 + k) * HW;
            unsigned so = sbase + (unsigned)(s * STG + k * 136 + c4) * 4u;
            cpa16(so + 0u * ARR * 4u, Ahb + go + n0 + c4);
            cpa16(so + 1u * ARR * 4u, Alb + go + n0 + c4);
            cpa16(so + 2u * ARR * 4u, Bhb + go + m0 + c4);
            cpa16(so + 3u * ARR * 4u, Blb + go + m0 + c4);
        }
        asm volatile("cp.async.commit_group;\n" ::: "memory");
    };

    float acc[4][4][4] = {};

    prefetch(0, 0);
    for (int it = 0; it < NIT; it++) {
        if (it + 1 < NIT) {
            prefetch(it + 1, (it + 1) & 1);
            asm volatile("cp.async.wait_group 1;\n" ::: "memory");
        } else {
            asm volatile("cp.async.wait_group 0;\n" ::: "memory");
        }
        __syncthreads();

        const unsigned* As  = sm + (it & 1) * STG;
        const unsigned* Asr = As + ARR;
        const unsigned* Bs  = As + 2 * ARR;
        const unsigned* Bsr = As + 3 * ARR;

#pragma unroll
        for (int c = 0; c < 4; c++) {
            int kc = c * 8;
            unsigned bb[4][2], br[4][2];
#pragma unroll
            for (int j = 0; j < 4; j++) {
                int col = wn * 32 + j * 8 + g;
                bb[j][0] = Bs[(kc + t) * 136 + col];
                bb[j][1] = Bs[(kc + t + 4) * 136 + col];
                br[j][0] = Bsr[(kc + t) * 136 + col];
                br[j][1] = Bsr[(kc + t + 4) * 136 + col];
            }
#pragma unroll
            for (int i = 0; i < 4; i++) {
                int row = wm * 64 + i * 16 + g;
                unsigned aa[4], ar[4];
                aa[0] = As[(kc + t) * 136 + row];
                aa[1] = As[(kc + t) * 136 + row + 8];
                aa[2] = As[(kc + t + 4) * 136 + row];
                aa[3] = As[(kc + t + 4) * 136 + row + 8];
                ar[0] = Asr[(kc + t) * 136 + row];
                ar[1] = Asr[(kc + t) * 136 + row + 8];
                ar[2] = Asr[(kc + t + 4) * 136 + row];
                ar[3] = Asr[(kc + t + 4) * 136 + row + 8];
#pragma unroll
                for (int j = 0; j < 4; j++) {
                    mma_tf32(acc[i][j], aa, bb[j]);
                    mma_tf32(acc[i][j], aa, br[j]);
                    mma_tf32(acc[i][j], ar, bb[j]);
                }
            }
        }
        __syncthreads();
    }

    // normal tile write
#pragma unroll
    for (int i = 0; i < 4; i++) {
        int r = n0 + wm * 64 + i * 16 + g;
#pragma unroll
        for (int j = 0; j < 4; j++) {
            int cc = m0 + wn * 32 + j * 8 + 2 * t;
            *(float2*)&Lb[(size_t)r * HW + cc] =
                make_float2(acc[i][j][0], acc[i][j][1]);
            *(float2*)&Lb[(size_t)(r + 8) * HW + cc] =
                make_float2(acc[i][j][2], acc[i][j][3]);
        }
    }
    // mirrored tile (sector-aligned scattered stores: 8 lanes hit one 32B sector)
    if (SYM && bx != by) {
#pragma unroll
        for (int i = 0; i < 4; i++) {
            int rr = n0 + wm * 64 + i * 16 + g;
#pragma unroll
            for (int j = 0; j < 4; j++) {
                int cc = m0 + wn * 32 + j * 8 + 2 * t;
                Lb[(size_t)cc * HW + rr]           = acc[i][j][0];
                Lb[(size_t)(cc + 1) * HW + rr]     = acc[i][j][1];
                Lb[(size_t)cc * HW + rr + 8]       = acc[i][j][2];
                Lb[(size_t)(cc + 1) * HW + rr + 8] = acc[i][j][3];
            }
        }
    }
}

// =====================================================================
// gemm_rr: C[m][n] = sum_k A[m][k] * B[k][n]  (proven R3 kernel)
// =====================================================================
template<bool THREE, int EPI>
__global__ __launch_bounds__(256, 2)
void gemm_rr(const float* __restrict__ A, const float* __restrict__ B,
             const float* __restrict__ bias,
             const float* __restrict__ U, const float* __restrict__ Rr,
             float* __restrict__ C,
             int K, int lda, size_t sA, size_t sB, size_t sC) {
    extern __shared__ unsigned sm[];
    unsigned* As  = sm;
    unsigned* Asr = As + 128 * 36;
    unsigned* Bs  = As + (THREE ? 2 : 1) * 128 * 36;
    unsigned* Bsr = Bs + 32 * 136;

    int b = blockIdx.z;
    const float* Ab = A + (size_t)b * sA;
    const float* Bb = B + (size_t)b * sB;
    int n0 = blockIdx.x * 128;
    int m0 = blockIdx.y * 128;
    int tid = threadIdx.x;
    int warp = tid >> 5, lane = tid & 31;
    int g = lane >> 2, t = lane & 3;
    int wm = warp >> 2, wn = warp & 3;
    int la_n = tid >> 3, la_k = (tid & 7) * 4;
    int lb_k = tid >> 5, lb_n = (tid & 31) * 4;

    float acc[4][4][4] = {};

    for (int k0 = 0; k0 < K; k0 += 32) {
#pragma unroll
        for (int u = 0; u < 4; u++) {
            int n = la_n + u * 32;
            float4 v = *(const float4*)&Ab[(size_t)(m0 + n) * lda + k0 + la_k];
            unsigned h0 = f2tf(v.x), h1 = f2tf(v.y), h2 = f2tf(v.z), h3 = f2tf(v.w);
            unsigned* p = &As[n * 36 + la_k];
            p[0] = h0; p[1] = h1; p[2] = h2; p[3] = h3;
            if (THREE) {
                unsigned* q = &Asr[n * 36 + la_k];
                q[0] = f2tf(v.x - __uint_as_float(h0));
                q[1] = f2tf(v.y - __uint_as_float(h1));
                q[2] = f2tf(v.z - __uint_as_float(h2));
                q[3] = f2tf(v.w - __uint_as_float(h3));
            }
        }
#pragma unroll
        for (int u = 0; u < 4; u++) {
            int k = lb_k + u * 8;
            float4 v = *(const float4*)&Bb[(size_t)(k0 + k) * CDIM + n0 + lb_n];
            unsigned h0 = f2tf(v.x), h1 = f2tf(v.y), h2 = f2tf(v.z), h3 = f2tf(v.w);
            unsigned* p = &Bs[k * 136 + lb_n];
            p[0] = h0; p[1] = h1; p[2] = h2; p[3] = h3;
            if (THREE) {
                unsigned* q = &Bsr[k * 136 + lb_n];
                q[0] = f2tf(v.x - __uint_as_float(h0));
                q[1] = f2tf(v.y - __uint_as_float(h1));
                q[2] = f2tf(v.z - __uint_as_float(h2));
                q[3] = f2tf(v.w - __uint_as_float(h3));
            }
        }
        __syncthreads();

#pragma unroll
        for (int c = 0; c < 4; c++) {
            int kc = c * 8;
            unsigned bb[4][2], br[4][2];
#pragma unroll
            for (int j = 0; j < 4; j++) {
                int col = wn * 32 + j * 8 + g;
                bb[j][0] = Bs[(kc + t) * 136 + col];
                bb[j][1] = Bs[(kc + t + 4) * 136 + col];
                if (THREE) {
                    br[j][0] = Bsr[(kc + t) * 136 + col];
                    br[j][1] = Bsr[(kc + t + 4) * 136 + col];
                }
            }
#pragma unroll
            for (int i = 0; i < 4; i++) {
                int row = wm * 64 + i * 16 + g;
                unsigned aa[4], ar[4];
                aa[0] = As[row * 36 + kc + t];
                aa[1] = As[(row + 8) * 36 + kc + t];
                aa[2] = As[row * 36 + kc + t + 4];
                aa[3] = As[(row + 8) * 36 + kc + t + 4];
                if (THREE) {
                    ar[0] = Asr[row * 36 + kc + t];
                    ar[1] = Asr[(row + 8) * 36 + kc + t];
                    ar[2] = Asr[row * 36 + kc + t + 4];
                    ar[3] = Asr[(row + 8) * 36 + kc + t + 4];
                }
#pragma unroll
                for (int j = 0; j < 4; j++) {
                    mma_tf32(acc[i][j], aa, bb[j]);
                    if (THREE) {
                        mma_tf32(acc[i][j], aa, br[j]);
                        mma_tf32(acc[i][j], ar, bb[j]);
                    }
                }
            }
        }
        __syncthreads();
    }

    float* Cb = C + (size_t)b * sC;
#pragma unroll
    for (int i = 0; i < 4; i++) {
        int r = m0 + wm * 64 + i * 16 + g;
#pragma unroll
        for (int j = 0; j < 4; j++) {
            int cc = n0 + wn * 32 + j * 8 + 2 * t;
            size_t o0 = (size_t)r * CDIM + cc;
            size_t o1 = (size_t)(r + 8) * CDIM + cc;
            if (EPI == 1) {
                float2 bv = *(const float2*)&bias[cc];
                float2 v0 = make_float2(fmaxf(acc[i][j][0] + bv.x, 0.f),
                                        fmaxf(acc[i][j][1] + bv.y, 0.f));
                float2 v1 = make_float2(fmaxf(acc[i][j][2] + bv.x, 0.f),
                                        fmaxf(acc[i][j][3] + bv.y, 0.f));
                *(float2*)&Cb[o0] = v0;
                *(float2*)&Cb[o1] = v1;
            } else {
                const float* Ub = U + (size_t)b * sC;
                const float* Rb = Rr + (size_t)b * sC;
                float2 u0 = *(const float2*)&Ub[o0], u1 = *(const float2*)&Ub[o1];
                float2 q0 = *(const float2*)&Rb[o0], q1 = *(const float2*)&Rb[o1];
                float2 v0 = make_float2(acc[i][j][0] + u0.x + q0.x,
                                        acc[i][j][1] + u0.y + q0.y);
                float2 v1 = make_float2(acc[i][j][2] + u1.x + q1.x,
                                        acc[i][j][3] + u1.y + q1.y);
                *(float2*)&Cb[o0] = v0;
                *(float2*)&Cb[o1] = v1;
            }
        }
    }
}

// ---------------- row softmax in place ----------------
__global__ void softmax_kernel(float* __restrict__ P) {
    float* row = P + ((size_t)blockIdx.y * HW + blockIdx.x) * HW;
    int t = threadIdx.x;
    __shared__ float red[16];
    float v[8];
    float mx = -1e30f;
#pragma unroll
    for (int i = 0; i < 8; i++) { v[i] = row[t + i * 512]; mx = fmaxf(mx, v[i]); }
    for (int o = 16; o; o >>= 1) mx = fmaxf(mx, __shfl_xor_sync(0xffffffffu, mx, o));
    int warp = t >> 5, lane = t & 31;
    if (lane == 0) red[warp] = mx;
    __syncthreads();
    if (warp == 0) {
        float m2 = red[lane & 15];
        for (int o = 8; o; o >>= 1) m2 = fmaxf(m2, __shfl_xor_sync(0xffffffffu, m2, o));
        if (lane == 0) red[0] = m2;
    }
    __syncthreads();
    mx = red[0];
    __syncthreads();
    float s = 0.f;
#pragma unroll
    for (int i = 0; i < 8; i++) { v[i] = __expf(v[i] - mx); s += v[i]; }
    for (int o = 16; o; o >>= 1) s += __shfl_xor_sync(0xffffffffu, s, o);
    if (lane == 0) red[warp] = s;
    __syncthreads();
    if (warp == 0) {
        float s2 = red[lane & 15];
        for (int o = 8; o; o >>= 1) s2 += __shfl_xor_sync(0xffffffffu, s2, o);
        if (lane == 0) red[0] = s2;
    }
    __syncthreads();
    float inv = 1.f / red[0];
#pragma unroll
    for (int i = 0; i < 8; i++) row[t + i * 512] = v[i] * inv;
}

// ---------------- column partial sums ----------------
__global__ void colsum_kernel(const float* __restrict__ P, float* __restrict__ part) {
    int b = blockIdx.z;
    int m = blockIdx.x * 256 + threadIdx.x;
    int r0 = blockIdx.y * 256;
    const float* Pb = P + (size_t)b * HW * HW;
    float s = 0.f;
#pragma unroll 8
    for (int r = 0; r < 256; r++) s += Pb[(size_t)(r0 + r) * HW + m];
    part[((size_t)b * 16 + blockIdx.y) * HW + m] = s;
}

__global__ void colinv_kernel(const float* __restrict__ part, float* __restrict__ colinv) {
    int i = blockIdx.x * 256 + threadIdx.x;
    int b = i >> 12, m = i & (HW - 1);
    float s = 0.f;
#pragma unroll
    for (int c2 = 0; c2 < 16; c2++) s += part[((size_t)b * 16 + c2) * HW + m];
    colinv[i] = 1.f / fmaxf(s, 1e-12f);
}

__global__ void scale_ax_kernel(float* __restrict__ ax, const float* __restrict__ colinv) {
    size_t f4 = (size_t)blockIdx.x * 256 + threadIdx.x;
    int row = (int)(f4 >> 6);
    float sc = colinv[row];
    float4 v = ((float4*)ax)[f4];
    v.x *= sc; v.y *= sc; v.z *= sc; v.w *= sc;
    ((float4*)ax)[f4] = v;
}

// ---------------- launch ----------------
extern "C" void kernel_launch(void* const* d_in, const int* in_sizes, int n_in,
                              void* d_out, int out_size) {
    (void)in_sizes; (void)n_in; (void)out_size;
    const float* skt = (const float*)d_in[0];
    const float* ref = (const float*)d_in[1];
    const float* Wa3 = (const float*)d_in[2];
    const float* ba3 = (const float*)d_in[3];
    const float* Wu3 = (const float*)d_in[4];
    const float* bu3 = (const float*)d_in[5];
    const float* Wa4 = (const float*)d_in[6];
    const float* ba4 = (const float*)d_in[7];
    const float* Wu4 = (const float*)d_in[8];
    const float* bu4 = (const float*)d_in[9];
    float* out = (float*)d_out;

    float *P, *ax, *ux, *gen, *gencn, *sktnc, *refnc, *colpart, *colinv;
    unsigned *hi0, *lo0, *hi1, *lo1;
    cudaGetSymbolAddress((void**)&P, g_P);
    cudaGetSymbolAddress((void**)&ax, g_ax);
    cudaGetSymbolAddress((void**)&ux, g_ux);
    cudaGetSymbolAddress((void**)&gen, g_gen);
    cudaGetSymbolAddress((void**)&gencn, g_gencn);
    cudaGetSymbolAddress((void**)&sktnc, g_sktnc);
    cudaGetSymbolAddress((void**)&refnc, g_refnc);
    cudaGetSymbolAddress((void**)&colpart, g_colpart);
    cudaGetSymbolAddress((void**)&colinv, g_colinv);
    cudaGetSymbolAddress((void**)&hi0, g_hi0);
    cudaGetSymbolAddress((void**)&lo0, g_lo0);
    cudaGetSymbolAddress((void**)&hi1, g_hi1);
    cudaGetSymbolAddress((void**)&lo1, g_lo1);

    const int SM3  = (2 * 128 * 36 + 2 * 32 * 136) * 4;   // 71680
    const int SM1  = (128 * 36 + 32 * 136) * 4;           // 35840
    const int SMLC = 2 * 4 * 32 * 136 * 4;                // 139264
    cudaFuncSetAttribute(gemm_rr<true, 1>,  cudaFuncAttributeMaxDynamicSharedMemorySize, SM3);
    cudaFuncSetAttribute(gemm_rr<true, 2>,  cudaFuncAttributeMaxDynamicSharedMemorySize, SM3);
    cudaFuncSetAttribute(gemm_rr<false, 1>, cudaFuncAttributeMaxDynamicSharedMemorySize, SM1);
    cudaFuncSetAttribute(gemm_rr<false, 2>, cudaFuncAttributeMaxDynamicSharedMemorySize, SM1);
    cudaFuncSetAttribute(logits_cp<false>,  cudaFuncAttributeMaxDynamicSharedMemorySize, SMLC);
    cudaFuncSetAttribute(logits_cp<true>,   cudaFuncAttributeMaxDynamicSharedMemorySize, SMLC);

    dim3 tb(32, 8);
    dim3 gLin(CDIM / 128, (BATCH * HW) / 128, 1);
    dim3 gLog(HW / 128, HW / 128, BATCH);
    dim3 gPax(CDIM / 128, HW / 128, BATCH);
    const int nSplit = (BATCH * HW * CDIM) / (4 * 256);

    // ===== layer 1 =====
    transpose_kernel<<<dim3(HW / 32, CDIM / 32, BATCH), tb>>>(skt, sktnc, CDIM, HW);
    transpose_kernel<<<dim3(HW / 32, CDIM / 32, BATCH), tb>>>(ref, refnc, CDIM, HW);
    split_kernel<<<nSplit, 256>>>(skt, hi0, lo0);
    split_kernel<<<nSplit, 256>>>(ref, hi1, lo1);
    gemm_rr<true, 1><<<gLin, 256, SM3>>>(refnc, Wa3, ba3, nullptr, nullptr, ax,
                                         CDIM, CDIM, 0, 0, 0);
    gemm_rr<true, 1><<<gLin, 256, SM3>>>(sktnc, Wu3, bu3, nullptr, nullptr, ux,
                                         CDIM, CDIM, 0, 0, 0);
    logits_cp<false><<<gLog, 256, SMLC>>>(hi0, lo0, hi1, lo1, P);
    softmax_kernel<<<dim3(HW, BATCH), 512>>>(P);
    colsum_kernel<<<dim3(HW / 256, 16, BATCH), 256>>>(P, colpart);
    colinv_kernel<<<(BATCH * HW) / 256, 256>>>(colpart, colinv);
    scale_ax_kernel<<<(BATCH * HW * CDIM) / (4 * 256), 256>>>(ax, colinv);
    gemm_rr<true, 2><<<gPax, 256, SM3>>>(P, ax, nullptr, ux, sktnc, gen,
                                         HW, HW,
                                         (size_t)HW * HW, (size_t)HW * CDIM, (size_t)HW * CDIM);

    // ===== layer 2 (logits symmetric: gen.genT) =====
    transpose_kernel<<<dim3(CDIM / 32, HW / 32, BATCH), tb>>>(gen, gencn, HW, CDIM);
    split_kernel<<<nSplit, 256>>>(gencn, hi0, lo0);
    gemm_rr<false, 1><<<gLin, 256, SM1>>>(gen, Wa4, ba4, nullptr, nullptr, ax,
                                          CDIM, CDIM, 0, 0, 0);
    gemm_rr<false, 1><<<gLin, 256, SM1>>>(gen, Wu4, bu4, nullptr, nullptr, ux,
                                          CDIM, CDIM, 0, 0, 0);
    logits_cp<true><<<gLog, 256, SMLC>>>(hi0, lo0, hi0, lo0, P);
    softmax_kernel<<<dim3(HW, BATCH), 512>>>(P);
    colsum_kernel<<<dim3(HW / 256, 16, BATCH), 256>>>(P, colpart);
    colinv_kernel<<<(BATCH * HW) / 256, 256>>>(colpart, colinv);
    scale_ax_kernel<<<(BATCH * HW * CDIM) / (4 * 256), 256>>>(ax, colinv);
    gemm_rr<false, 2><<<gPax, 256, SM1>>>(P, ax, nullptr, ux, gen, out,
                                          HW, HW,
                                          (size_t)HW * HW, (size_t)HW * CDIM, (size_t)HW * CDIM);
}

// round 6
// speedup vs baseline: 1.0604x; 1.0011x over previous
#include <cuda_runtime.h>
#include <math.h>

#define BATCH 4
#define CDIM  256
#define HW    4096

// ---------------- scratch (no allocations allowed) ----------------
static __device__ float g_P[(size_t)BATCH * HW * HW];          // 268 MB: logits / probs
static __device__ float g_ax[(size_t)BATCH * HW * CDIM];
static __device__ float g_ux[(size_t)BATCH * HW * CDIM];
static __device__ float g_gen[(size_t)BATCH * HW * CDIM];      // gen, n-major (b,hw,c)
static __device__ float g_gencn[(size_t)BATCH * HW * CDIM];    // gen, c-major (b,c,hw)
static __device__ float g_sktnc[(size_t)BATCH * HW * CDIM];
static __device__ float g_refnc[(size_t)BATCH * HW * CDIM];
static __device__ float g_colpart[(size_t)BATCH * 16 * HW];
static __device__ float g_colinv[(size_t)BATCH * HW];
// tf32 hi/lo pre-split operands for logits GEMMs
static __device__ unsigned g_hi0[(size_t)BATCH * HW * CDIM];
static __device__ unsigned g_lo0[(size_t)BATCH * HW * CDIM];
static __device__ unsigned g_hi1[(size_t)BATCH * HW * CDIM];
static __device__ unsigned g_lo1[(size_t)BATCH * HW * CDIM];

// ---------------- tf32 helpers ----------------
__device__ __forceinline__ unsigned f2tf(float x) {
    unsigned r;
    asm("cvt.rna.tf32.f32 %0, %1;" : "=r"(r) : "f"(x));
    return r;
}

__device__ __forceinline__ void mma_tf32(float* d, const unsigned* a, const unsigned* b) {
    asm("mma.sync.aligned.m16n8k8.row.col.f32.tf32.tf32.f32 "
        "{%0,%1,%2,%3},{%4,%5,%6,%7},{%8,%9},{%0,%1,%2,%3};"
        : "+f"(d[0]), "+f"(d[1]), "+f"(d[2]), "+f"(d[3])
        : "r"(a[0]), "r"(a[1]), "r"(a[2]), "r"(a[3]), "r"(b[0]), "r"(b[1]));
}

__device__ __forceinline__ void cpa16(unsigned saddr, const void* g) {
    asm volatile("cp.async.cg.shared.global [%0], [%1], 16;\n" :: "r"(saddr), "l"(g));
}

// ---------------- split: float -> (tf32 hi, tf32 lo) ----------------
__global__ void split_kernel(const float* __restrict__ in, unsigned* __restrict__ hi,
                             unsigned* __restrict__ lo) {
    size_t i = (size_t)blockIdx.x * 256 + threadIdx.x;   // float4 index
    float4 v = ((const float4*)in)[i];
    uint4 h, l;
    h.x = f2tf(v.x); l.x = f2tf(v.x - __uint_as_float(h.x));
    h.y = f2tf(v.y); l.y = f2tf(v.y - __uint_as_float(h.y));
    h.z = f2tf(v.z); l.z = f2tf(v.z - __uint_as_float(h.z));
    h.w = f2tf(v.w); l.w = f2tf(v.w - __uint_as_float(h.w));
    ((uint4*)hi)[i] = h;
    ((uint4*)lo)[i] = l;
}

// ---------------- transpose: in (b,R,S) -> out (b,S,R) ----------------
__global__ void transpose_kernel(const float* __restrict__ in, float* __restrict__ out,
                                 int R, int S) {
    __shared__ float tile[32][33];
    int b = blockIdx.z;
    int s0 = blockIdx.x * 32, r0 = blockIdx.y * 32;
    const float* inb = in + (size_t)b * R * S;
    float* outb = out + (size_t)b * R * S;
    int tx = threadIdx.x, ty = threadIdx.y;
#pragma unroll
    for (int i = 0; i < 32; i += 8)
        tile[ty + i][tx] = inb[(size_t)(r0 + ty + i) * S + s0 + tx];
    __syncthreads();
#pragma unroll
    for (int i = 0; i < 32; i += 8)
        outb[(size_t)(s0 + ty + i) * R + r0 + tx] = tile[tx][ty + i];
}

// =====================================================================
// logits_cp: L[n][m] = sum_k A[k][n] * B[k][m], 3xTF32 from pre-split
// hi/lo operands, cp.async double-buffered. SYM: compute only upper
// triangle of blocks, mirror off-diagonal tiles (L symmetric).
// CTA 128x128, 8 warps 2x4, BK=32, K=CDIM=256.
// =====================================================================
template<bool SYM>
__global__ __launch_bounds__(256)
void logits_cp(const unsigned* __restrict__ Ah, const unsigned* __restrict__ Al,
               const unsigned* __restrict__ Bh, const unsigned* __restrict__ Bl,
               float* __restrict__ L) {
    extern __shared__ unsigned sm[];
    constexpr int ARR = 32 * 136;      // words per array
    constexpr int STG = 4 * ARR;       // words per stage
    constexpr int NIT = CDIM / 32;     // 8

    int bx = blockIdx.x, by = blockIdx.y, b = blockIdx.z;
    if (SYM && bx < by) return;
    int m0 = bx * 128;   // cols of L
    int n0 = by * 128;   // rows of L

    const unsigned* Ahb = Ah + (size_t)b * CDIM * HW;
    const unsigned* Alb = Al + (size_t)b * CDIM * HW;
    const unsigned* Bhb = Bh + (size_t)b * CDIM * HW;
    const unsigned* Blb = Bl + (size_t)b * CDIM * HW;
    float* Lb = L + (size_t)b * HW * HW;

    unsigned sbase;
    asm("{ .reg .u64 t0; cvta.to.shared.u64 t0, %1; cvt.u32.u64 %0, t0; }"
        : "=r"(sbase) : "l"(sm));

    int tid = threadIdx.x;
    int warp = tid >> 5, lane = tid & 31;
    int g = lane >> 2, t = lane & 3;
    int wm = warp >> 2, wn = warp & 3;

    auto prefetch = [&](int it, int s) {
        int k0 = it * 32;
#pragma unroll
        for (int q = 0; q < 4; q++) {
            int f = tid + q * 256;
            int k = f >> 5, c4 = (f & 31) * 4;
            size_t go = (size_t)(k0 + k) * HW;
            unsigned so = sbase + (unsigned)(s * STG + k * 136 + c4) * 4u;
            cpa16(so + 0u * ARR * 4u, Ahb + go + n0 + c4);
            cpa16(so + 1u * ARR * 4u, Alb + go + n0 + c4);
            cpa16(so + 2u * ARR * 4u, Bhb + go + m0 + c4);
            cpa16(so + 3u * ARR * 4u, Blb + go + m0 + c4);
        }
        asm volatile("cp.async.commit_group;\n" ::: "memory");
    };

    float acc[4][4][4] = {};

    prefetch(0, 0);
    for (int it = 0; it < NIT; it++) {
        if (it + 1 < NIT) {
            prefetch(it + 1, (it + 1) & 1);
            asm volatile("cp.async.wait_group 1;\n" ::: "memory");
        } else {
            asm volatile("cp.async.wait_group 0;\n" ::: "memory");
        }
        __syncthreads();

        const unsigned* As  = sm + (it & 1) * STG;
        const unsigned* Asr = As + ARR;
        const unsigned* Bs  = As + 2 * ARR;
        const unsigned* Bsr = As + 3 * ARR;

#pragma unroll
        for (int c = 0; c < 4; c++) {
            int kc = c * 8;
            unsigned bb[4][2], br[4][2];
#pragma unroll
            for (int j = 0; j < 4; j++) {
                int col = wn * 32 + j * 8 + g;
                bb[j][0] = Bs[(kc + t) * 136 + col];
                bb[j][1] = Bs[(kc + t + 4) * 136 + col];
                br[j][0] = Bsr[(kc + t) * 136 + col];
                br[j][1] = Bsr[(kc + t + 4) * 136 + col];
            }
#pragma unroll
            for (int i = 0; i < 4; i++) {
                int row = wm * 64 + i * 16 + g;
                unsigned aa[4], ar[4];
                aa[0] = As[(kc + t) * 136 + row];
                aa[1] = As[(kc + t) * 136 + row + 8];
                aa[2] = As[(kc + t + 4) * 136 + row];
                aa[3] = As[(kc + t + 4) * 136 + row + 8];
                ar[0] = Asr[(kc + t) * 136 + row];
                ar[1] = Asr[(kc + t) * 136 + row + 8];
                ar[2] = Asr[(kc + t + 4) * 136 + row];
                ar[3] = Asr[(kc + t + 4) * 136 + row + 8];
#pragma unroll
                for (int j = 0; j < 4; j++) {
                    mma_tf32(acc[i][j], aa, bb[j]);
                    mma_tf32(acc[i][j], aa, br[j]);
                    mma_tf32(acc[i][j], ar, bb[j]);
                }
            }
        }
        __syncthreads();
    }

    // normal tile write
#pragma unroll
    for (int i = 0; i < 4; i++) {
        int r = n0 + wm * 64 + i * 16 + g;
#pragma unroll
        for (int j = 0; j < 4; j++) {
            int cc = m0 + wn * 32 + j * 8 + 2 * t;
            *(float2*)&Lb[(size_t)r * HW + cc] =
                make_float2(acc[i][j][0], acc[i][j][1]);
            *(float2*)&Lb[(size_t)(r + 8) * HW + cc] =
                make_float2(acc[i][j][2], acc[i][j][3]);
        }
    }
    // mirrored tile (sector-aligned scattered stores: 8 lanes hit one 32B sector)
    if (SYM && bx != by) {
#pragma unroll
        for (int i = 0; i < 4; i++) {
            int rr = n0 + wm * 64 + i * 16 + g;
#pragma unroll
            for (int j = 0; j < 4; j++) {
                int cc = m0 + wn * 32 + j * 8 + 2 * t;
                Lb[(size_t)cc * HW + rr]           = acc[i][j][0];
                Lb[(size_t)(cc + 1) * HW + rr]     = acc[i][j][1];
                Lb[(size_t)cc * HW + rr + 8]       = acc[i][j][2];
                Lb[(size_t)(cc + 1) * HW + rr + 8] = acc[i][j][3];
            }
        }
    }
}

// =====================================================================
// gemm_rr: C[m][n] = sum_k A[m][k] * B[k][n]  (proven R3 kernel)
// =====================================================================
template<bool THREE, int EPI>
__global__ __launch_bounds__(256, 2)
void gemm_rr(const float* __restrict__ A, const float* __restrict__ B,
             const float* __restrict__ bias,
             const float* __restrict__ U, const float* __restrict__ Rr,
             float* __restrict__ C,
             int K, int lda, size_t sA, size_t sB, size_t sC) {
    extern __shared__ unsigned sm[];
    unsigned* As  = sm;
    unsigned* Asr = As + 128 * 36;
    unsigned* Bs  = As + (THREE ? 2 : 1) * 128 * 36;
    unsigned* Bsr = Bs + 32 * 136;

    int b = blockIdx.z;
    const float* Ab = A + (size_t)b * sA;
    const float* Bb = B + (size_t)b * sB;
    int n0 = blockIdx.x * 128;
    int m0 = blockIdx.y * 128;
    int tid = threadIdx.x;
    int warp = tid >> 5, lane = tid & 31;
    int g = lane >> 2, t = lane & 3;
    int wm = warp >> 2, wn = warp & 3;
    int la_n = tid >> 3, la_k = (tid & 7) * 4;
    int lb_k = tid >> 5, lb_n = (tid & 31) * 4;

    float acc[4][4][4] = {};

    for (int k0 = 0; k0 < K; k0 += 32) {
#pragma unroll
        for (int u = 0; u < 4; u++) {
            int n = la_n + u * 32;
            float4 v = *(const float4*)&Ab[(size_t)(m0 + n) * lda + k0 + la_k];
            unsigned h0 = f2tf(v.x), h1 = f2tf(v.y), h2 = f2tf(v.z), h3 = f2tf(v.w);
            unsigned* p = &As[n * 36 + la_k];
            p[0] = h0; p[1] = h1; p[2] = h2; p[3] = h3;
            if (THREE) {
                unsigned* q = &Asr[n * 36 + la_k];
                q[0] = f2tf(v.x - __uint_as_float(h0));
                q[1] = f2tf(v.y - __uint_as_float(h1));
                q[2] = f2tf(v.z - __uint_as_float(h2));
                q[3] = f2tf(v.w - __uint_as_float(h3));
            }
        }
#pragma unroll
        for (int u = 0; u < 4; u++) {
            int k = lb_k + u * 8;
            float4 v = *(const float4*)&Bb[(size_t)(k0 + k) * CDIM + n0 + lb_n];
            unsigned h0 = f2tf(v.x), h1 = f2tf(v.y), h2 = f2tf(v.z), h3 = f2tf(v.w);
            unsigned* p = &Bs[k * 136 + lb_n];
            p[0] = h0; p[1] = h1; p[2] = h2; p[3] = h3;
            if (THREE) {
                unsigned* q = &Bsr[k * 136 + lb_n];
                q[0] = f2tf(v.x - __uint_as_float(h0));
                q[1] = f2tf(v.y - __uint_as_float(h1));
                q[2] = f2tf(v.z - __uint_as_float(h2));
                q[3] = f2tf(v.w - __uint_as_float(h3));
            }
        }
        __syncthreads();

#pragma unroll
        for (int c = 0; c < 4; c++) {
            int kc = c * 8;
            unsigned bb[4][2], br[4][2];
#pragma unroll
            for (int j = 0; j < 4; j++) {
                int col = wn * 32 + j * 8 + g;
                bb[j][0] = Bs[(kc + t) * 136 + col];
                bb[j][1] = Bs[(kc + t + 4) * 136 + col];
                if (THREE) {
                    br[j][0] = Bsr[(kc + t) * 136 + col];
                    br[j][1] = Bsr[(kc + t + 4) * 136 + col];
                }
            }
#pragma unroll
            for (int i = 0; i < 4; i++) {
                int row = wm * 64 + i * 16 + g;
                unsigned aa[4], ar[4];
                aa[0] = As[row * 36 + kc + t];
                aa[1] = As[(row + 8) * 36 + kc + t];
                aa[2] = As[row * 36 + kc + t + 4];
                aa[3] = As[(row + 8) * 36 + kc + t + 4];
                if (THREE) {
                    ar[0] = Asr[row * 36 + kc + t];
                    ar[1] = Asr[(row + 8) * 36 + kc + t];
                    ar[2] = Asr[row * 36 + kc + t + 4];
                    ar[3] = Asr[(row + 8) * 36 + kc + t + 4];
                }
#pragma unroll
                for (int j = 0; j < 4; j++) {
                    mma_tf32(acc[i][j], aa, bb[j]);
                    if (THREE) {
                        mma_tf32(acc[i][j], aa, br[j]);
                        mma_tf32(acc[i][j], ar, bb[j]);
                    }
                }
            }
        }
        __syncthreads();
    }

    float* Cb = C + (size_t)b * sC;
#pragma unroll
    for (int i = 0; i < 4; i++) {
        int r = m0 + wm * 64 + i * 16 + g;
#pragma unroll
        for (int j = 0; j < 4; j++) {
            int cc = n0 + wn * 32 + j * 8 + 2 * t;
            size_t o0 = (size_t)r * CDIM + cc;
            size_t o1 = (size_t)(r + 8) * CDIM + cc;
            if (EPI == 1) {
                float2 bv = *(const float2*)&bias[cc];
                float2 v0 = make_float2(fmaxf(acc[i][j][0] + bv.x, 0.f),
                                        fmaxf(acc[i][j][1] + bv.y, 0.f));
                float2 v1 = make_float2(fmaxf(acc[i][j][2] + bv.x, 0.f),
                                        fmaxf(acc[i][j][3] + bv.y, 0.f));
                *(float2*)&Cb[o0] = v0;
                *(float2*)&Cb[o1] = v1;
            } else {
                const float* Ub = U + (size_t)b * sC;
                const float* Rb = Rr + (size_t)b * sC;
                float2 u0 = *(const float2*)&Ub[o0], u1 = *(const float2*)&Ub[o1];
                float2 q0 = *(const float2*)&Rb[o0], q1 = *(const float2*)&Rb[o1];
                float2 v0 = make_float2(acc[i][j][0] + u0.x + q0.x,
                                        acc[i][j][1] + u0.y + q0.y);
                float2 v1 = make_float2(acc[i][j][2] + u1.x + q1.x,
                                        acc[i][j][3] + u1.y + q1.y);
                *(float2*)&Cb[o0] = v0;
                *(float2*)&Cb[o1] = v1;
            }
        }
    }
}

// ---------------- row softmax in place ----------------
__global__ void softmax_kernel(float* __restrict__ P) {
    float* row = P + ((size_t)blockIdx.y * HW + blockIdx.x) * HW;
    int t = threadIdx.x;
    __shared__ float red[16];
    float v[8];
    float mx = -1e30f;
#pragma unroll
    for (int i = 0; i < 8; i++) { v[i] = row[t + i * 512]; mx = fmaxf(mx, v[i]); }
    for (int o = 16; o; o >>= 1) mx = fmaxf(mx, __shfl_xor_sync(0xffffffffu, mx, o));
    int warp = t >> 5, lane = t & 31;
    if (lane == 0) red[warp] = mx;
    __syncthreads();
    if (warp == 0) {
        float m2 = red[lane & 15];
        for (int o = 8; o; o >>= 1) m2 = fmaxf(m2, __shfl_xor_sync(0xffffffffu, m2, o));
        if (lane == 0) red[0] = m2;
    }
    __syncthreads();
    mx = red[0];
    __syncthreads();
    float s = 0.f;
#pragma unroll
    for (int i = 0; i < 8; i++) { v[i] = __expf(v[i] - mx); s += v[i]; }
    for (int o = 16; o; o >>= 1) s += __shfl_xor_sync(0xffffffffu, s, o);
    if (lane == 0) red[warp] = s;
    __syncthreads();
    if (warp == 0) {
        float s2 = red[lane & 15];
        for (int o = 8; o; o >>= 1) s2 += __shfl_xor_sync(0xffffffffu, s2, o);
        if (lane == 0) red[0] = s2;
    }
    __syncthreads();
    float inv = 1.f / red[0];
#pragma unroll
    for (int i = 0; i < 8; i++) row[t + i * 512] = v[i] * inv;
}

// ---------------- column partial sums ----------------
__global__ void colsum_kernel(const float* __restrict__ P, float* __restrict__ part) {
    int b = blockIdx.z;
    int m = blockIdx.x * 256 + threadIdx.x;
    int r0 = blockIdx.y * 256;
    const float* Pb = P + (size_t)b * HW * HW;
    float s = 0.f;
#pragma unroll 8
    for (int r = 0; r < 256; r++) s += Pb[(size_t)(r0 + r) * HW + m];
    part[((size_t)b * 16 + blockIdx.y) * HW + m] = s;
}

__global__ void colinv_kernel(const float* __restrict__ part, float* __restrict__ colinv) {
    int i = blockIdx.x * 256 + threadIdx.x;
    int b = i >> 12, m = i & (HW - 1);
    float s = 0.f;
#pragma unroll
    for (int c2 = 0; c2 < 16; c2++) s += part[((size_t)b * 16 + c2) * HW + m];
    colinv[i] = 1.f / fmaxf(s, 1e-12f);
}

__global__ void scale_ax_kernel(float* __restrict__ ax, const float* __restrict__ colinv) {
    size_t f4 = (size_t)blockIdx.x * 256 + threadIdx.x;
    int row = (int)(f4 >> 6);
    float sc = colinv[row];
    float4 v = ((float4*)ax)[f4];
    v.x *= sc; v.y *= sc; v.z *= sc; v.w *= sc;
    ((float4*)ax)[f4] = v;
}

// ---------------- launch ----------------
extern "C" void kernel_launch(void* const* d_in, const int* in_sizes, int n_in,
                              void* d_out, int out_size) {
    (void)in_sizes; (void)n_in; (void)out_size;
    const float* skt = (const float*)d_in[0];
    const float* ref = (const float*)d_in[1];
    const float* Wa3 = (const float*)d_in[2];
    const float* ba3 = (const float*)d_in[3];
    const float* Wu3 = (const float*)d_in[4];
    const float* bu3 = (const float*)d_in[5];
    const float* Wa4 = (const float*)d_in[6];
    const float* ba4 = (const float*)d_in[7];
    const float* Wu4 = (const float*)d_in[8];
    const float* bu4 = (const float*)d_in[9];
    float* out = (float*)d_out;

    float *P, *ax, *ux, *gen, *gencn, *sktnc, *refnc, *colpart, *colinv;
    unsigned *hi0, *lo0, *hi1, *lo1;
    cudaGetSymbolAddress((void**)&P, g_P);
    cudaGetSymbolAddress((void**)&ax, g_ax);
    cudaGetSymbolAddress((void**)&ux, g_ux);
    cudaGetSymbolAddress((void**)&gen, g_gen);
    cudaGetSymbolAddress((void**)&gencn, g_gencn);
    cudaGetSymbolAddress((void**)&sktnc, g_sktnc);
    cudaGetSymbolAddress((void**)&refnc, g_refnc);
    cudaGetSymbolAddress((void**)&colpart, g_colpart);
    cudaGetSymbolAddress((void**)&colinv, g_colinv);
    cudaGetSymbolAddress((void**)&hi0, g_hi0);
    cudaGetSymbolAddress((void**)&lo0, g_lo0);
    cudaGetSymbolAddress((void**)&hi1, g_hi1);
    cudaGetSymbolAddress((void**)&lo1, g_lo1);

    const int SM3  = (2 * 128 * 36 + 2 * 32 * 136) * 4;   // 71680
    const int SM1  = (128 * 36 + 32 * 136) * 4;           // 35840
    const int SMLC = 2 * 4 * 32 * 136 * 4;                // 139264
    cudaFuncSetAttribute(gemm_rr<true, 1>,  cudaFuncAttributeMaxDynamicSharedMemorySize, SM3);
    cudaFuncSetAttribute(gemm_rr<true, 2>,  cudaFuncAttributeMaxDynamicSharedMemorySize, SM3);
    cudaFuncSetAttribute(gemm_rr<false, 1>, cudaFuncAttributeMaxDynamicSharedMemorySize, SM1);
    cudaFuncSetAttribute(gemm_rr<false, 2>, cudaFuncAttributeMaxDynamicSharedMemorySize, SM1);
    cudaFuncSetAttribute(logits_cp<false>,  cudaFuncAttributeMaxDynamicSharedMemorySize, SMLC);
    cudaFuncSetAttribute(logits_cp<true>,   cudaFuncAttributeMaxDynamicSharedMemorySize, SMLC);

    dim3 tb(32, 8);
    dim3 gLin(CDIM / 128, (BATCH * HW) / 128, 1);
    dim3 gLog(HW / 128, HW / 128, BATCH);
    dim3 gPax(CDIM / 128, HW / 128, BATCH);
    const int nSplit = (BATCH * HW * CDIM) / (4 * 256);

    // ===== layer 1 =====
    transpose_kernel<<<dim3(HW / 32, CDIM / 32, BATCH), tb>>>(skt, sktnc, CDIM, HW);
    transpose_kernel<<<dim3(HW / 32, CDIM / 32, BATCH), tb>>>(ref, refnc, CDIM, HW);
    split_kernel<<<nSplit, 256>>>(skt, hi0, lo0);
    split_kernel<<<nSplit, 256>>>(ref, hi1, lo1);
    gemm_rr<true, 1><<<gLin, 256, SM3>>>(refnc, Wa3, ba3, nullptr, nullptr, ax,
                                         CDIM, CDIM, 0, 0, 0);
    gemm_rr<true, 1><<<gLin, 256, SM3>>>(sktnc, Wu3, bu3, nullptr, nullptr, ux,
                                         CDIM, CDIM, 0, 0, 0);
    logits_cp<false><<<gLog, 256, SMLC>>>(hi0, lo0, hi1, lo1, P);
    softmax_kernel<<<dim3(HW, BATCH), 512>>>(P);
    colsum_kernel<<<dim3(HW / 256, 16, BATCH), 256>>>(P, colpart);
    colinv_kernel<<<(BATCH * HW) / 256, 256>>>(colpart, colinv);
    scale_ax_kernel<<<(BATCH * HW * CDIM) / (4 * 256), 256>>>(ax, colinv);
    gemm_rr<true, 2><<<gPax, 256, SM3>>>(P, ax, nullptr, ux, sktnc, gen,
                                         HW, HW,
                                         (size_t)HW * HW, (size_t)HW * CDIM, (size_t)HW * CDIM);

    // ===== layer 2 (logits symmetric: gen.genT) =====
    transpose_kernel<<<dim3(CDIM / 32, HW / 32, BATCH), tb>>>(gen, gencn, HW, CDIM);
    split_kernel<<<nSplit, 256>>>(gencn, hi0, lo0);
    gemm_rr<false, 1><<<gLin, 256, SM1>>>(gen, Wa4, ba4, nullptr, nullptr, ax,
                                          CDIM, CDIM, 0, 0, 0);
    gemm_rr<false, 1><<<gLin, 256, SM1>>>(gen, Wu4, bu4, nullptr, nullptr, ux,
                                          CDIM, CDIM, 0, 0, 0);
    logits_cp<true><<<gLog, 256, SMLC>>>(hi0, lo0, hi0, lo0, P);
    softmax_kernel<<<dim3(HW, BATCH), 512>>>(P);
    colsum_kernel<<<dim3(HW / 256, 16, BATCH), 256>>>(P, colpart);
    colinv_kernel<<<(BATCH * HW) / 256, 256>>>(colpart, colinv);
    scale_ax_kernel<<<(BATCH * HW * CDIM) / (4 * 256), 256>>>(ax, colinv);
    gemm_rr<false, 2><<<gPax, 256, SM1>>>(P, ax, nullptr, ux, gen, out,
                                          HW, HW,
                                          (size_t)HW * HW, (size_t)HW * CDIM, (size_t)HW * CDIM);
}

// round 7
// speedup vs baseline: 1.0623x; 1.0018x over previous
#include <cuda_runtime.h>
#include <math.h>

#define BATCH 4
#define CDIM  256
#define HW    4096

// ---------------- scratch (no allocations allowed) ----------------
static __device__ float g_P[(size_t)BATCH * HW * HW];          // 268 MB: logits / probs
static __device__ float g_ax[(size_t)BATCH * HW * CDIM];
static __device__ float g_ux[(size_t)BATCH * HW * CDIM];
static __device__ float g_gen[(size_t)BATCH * HW * CDIM];      // gen, n-major (b,hw,c)
static __device__ float g_gencn[(size_t)BATCH * HW * CDIM];    // gen, c-major (b,c,hw)
static __device__ float g_sktnc[(size_t)BATCH * HW * CDIM];
static __device__ float g_refnc[(size_t)BATCH * HW * CDIM];
static __device__ float g_colpart[(size_t)BATCH * 16 * HW];
static __device__ float g_colinv[(size_t)BATCH * HW];
// tf32 hi/lo pre-split operands for logits GEMMs
static __device__ unsigned g_hi0[(size_t)BATCH * HW * CDIM];
static __device__ unsigned g_lo0[(size_t)BATCH * HW * CDIM];
static __device__ unsigned g_hi1[(size_t)BATCH * HW * CDIM];
static __device__ unsigned g_lo1[(size_t)BATCH * HW * CDIM];

// ---------------- tf32 helpers ----------------
__device__ __forceinline__ unsigned f2tf(float x) {
    unsigned r;
    asm("cvt.rna.tf32.f32 %0, %1;" : "=r"(r) : "f"(x));
    return r;
}

__device__ __forceinline__ void mma_tf32(float* d, const unsigned* a, const unsigned* b) {
    asm("mma.sync.aligned.m16n8k8.row.col.f32.tf32.tf32.f32 "
        "{%0,%1,%2,%3},{%4,%5,%6,%7},{%8,%9},{%0,%1,%2,%3};"
        : "+f"(d[0]), "+f"(d[1]), "+f"(d[2]), "+f"(d[3])
        : "r"(a[0]), "r"(a[1]), "r"(a[2]), "r"(a[3]), "r"(b[0]), "r"(b[1]));
}

__device__ __forceinline__ void cpa16(unsigned saddr, const void* g) {
    asm volatile("cp.async.cg.shared.global [%0], [%1], 16;\n" :: "r"(saddr), "l"(g));
}

// ---------------- split: float -> (tf32 hi, tf32 lo) ----------------
__global__ void split_kernel(const float* __restrict__ in, unsigned* __restrict__ hi,
                             unsigned* __restrict__ lo) {
    size_t i = (size_t)blockIdx.x * 256 + threadIdx.x;   // float4 index
    float4 v = ((const float4*)in)[i];
    uint4 h, l;
    h.x = f2tf(v.x); l.x = f2tf(v.x - __uint_as_float(h.x));
    h.y = f2tf(v.y); l.y = f2tf(v.y - __uint_as_float(h.y));
    h.z = f2tf(v.z); l.z = f2tf(v.z - __uint_as_float(h.z));
    h.w = f2tf(v.w); l.w = f2tf(v.w - __uint_as_float(h.w));
    ((uint4*)hi)[i] = h;
    ((uint4*)lo)[i] = l;
}

// ---------------- transpose: in (b,R,S) -> out (b,S,R) ----------------
__global__ void transpose_kernel(const float* __restrict__ in, float* __restrict__ out,
                                 int R, int S) {
    __shared__ float tile[32][33];
    int b = blockIdx.z;
    int s0 = blockIdx.x * 32, r0 = blockIdx.y * 32;
    const float* inb = in + (size_t)b * R * S;
    float* outb = out + (size_t)b * R * S;
    int tx = threadIdx.x, ty = threadIdx.y;
#pragma unroll
    for (int i = 0; i < 32; i += 8)
        tile[ty + i][tx] = inb[(size_t)(r0 + ty + i) * S + s0 + tx];
    __syncthreads();
#pragma unroll
    for (int i = 0; i < 32; i += 8)
        outb[(size_t)(s0 + ty + i) * R + r0 + tx] = tile[tx][ty + i];
}

// =====================================================================
// logits_cp: L[n][m] = sum_k A[k][n] * B[k][m], 3xTF32 from pre-split
// hi/lo operands, cp.async double-buffered. SYM: compute only upper
// triangle of blocks, mirror off-diagonal tiles (L symmetric).
// CTA 128x128, 8 warps 2x4, BK=32, K=CDIM=256.
// =====================================================================
template<bool SYM>
__global__ __launch_bounds__(256)
void logits_cp(const unsigned* __restrict__ Ah, const unsigned* __restrict__ Al,
               const unsigned* __restrict__ Bh, const unsigned* __restrict__ Bl,
               float* __restrict__ L) {
    extern __shared__ unsigned sm[];
    constexpr int ARR = 32 * 136;      // words per array
    constexpr int STG = 4 * ARR;       // words per stage
    constexpr int NIT = CDIM / 32;     // 8

    int bx = blockIdx.x, by = blockIdx.y, b = blockIdx.z;
    if (SYM && bx < by) return;
    int m0 = bx * 128;   // cols of L
    int n0 = by * 128;   // rows of L

    const unsigned* Ahb = Ah + (size_t)b * CDIM * HW;
    const unsigned* Alb = Al + (size_t)b * CDIM * HW;
    const unsigned* Bhb = Bh + (size_t)b * CDIM * HW;
    const unsigned* Blb = Bl + (size_t)b * CDIM * HW;
    float* Lb = L + (size_t)b * HW * HW;

    unsigned sbase;
    asm("{ .reg .u64 t0; cvta.to.shared.u64 t0, %1; cvt.u32.u64 %0, t0; }"
        : "=r"(sbase) : "l"(sm));

    int tid = threadIdx.x;
    int warp = tid >> 5, lane = tid & 31;
    int g = lane >> 2, t = lane & 3;
    int wm = warp >> 2, wn = warp & 3;

    auto prefetch = [&](int it, int s) {
        int k0 = it * 32;
#pragma unroll
        for (int q = 0; q < 4; q++) {
            int f = tid + q * 256;
            int k = f >> 5, c4 = (f & 31) * 4;
            size_t go = (size_t)(k0 + k) * HW;
            unsigned so = sbase + (unsigned)(s * STG + k * 136 + c4) * 4u;
            cpa16(so + 0u * ARR * 4u, Ahb + go + n0 + c4);
            cpa16(so + 1u * ARR * 4u, Alb + go + n0 + c4);
            cpa16(so + 2u * ARR * 4u, Bhb + go + m0 + c4);
            cpa16(so + 3u * ARR * 4u, Blb + go + m0 + c4);
        }
        asm volatile("cp.async.commit_group;\n" ::: "memory");
    };

    float acc[4][4][4] = {};

    prefetch(0, 0);
    for (int it = 0; it < NIT; it++) {
        if (it + 1 < NIT) {
            prefetch(it + 1, (it + 1) & 1);
            asm volatile("cp.async.wait_group 1;\n" ::: "memory");
        } else {
            asm volatile("cp.async.wait_group 0;\n" ::: "memory");
        }
        __syncthreads();

        const unsigned* As  = sm + (it & 1) * STG;
        const unsigned* Asr = As + ARR;
        const unsigned* Bs  = As + 2 * ARR;
        const unsigned* Bsr = As + 3 * ARR;

#pragma unroll
        for (int c = 0; c < 4; c++) {
            int kc = c * 8;
            unsigned bb[4][2], br[4][2];
#pragma unroll
            for (int j = 0; j < 4; j++) {
                int col = wn * 32 + j * 8 + g;
                bb[j][0] = Bs[(kc + t) * 136 + col];
                bb[j][1] = Bs[(kc + t + 4) * 136 + col];
                br[j][0] = Bsr[(kc + t) * 136 + col];
                br[j][1] = Bsr[(kc + t + 4) * 136 + col];
            }
#pragma unroll
            for (int i = 0; i < 4; i++) {
                int row = wm * 64 + i * 16 + g;
                unsigned aa[4], ar[4];
                aa[0] = As[(kc + t) * 136 + row];
                aa[1] = As[(kc + t) * 136 + row + 8];
                aa[2] = As[(kc + t + 4) * 136 + row];
                aa[3] = As[(kc + t + 4) * 136 + row + 8];
                ar[0] = Asr[(kc + t) * 136 + row];
                ar[1] = Asr[(kc + t) * 136 + row + 8];
                ar[2] = Asr[(kc + t + 4) * 136 + row];
                ar[3] = Asr[(kc + t + 4) * 136 + row + 8];
#pragma unroll
                for (int j = 0; j < 4; j++) {
                    mma_tf32(acc[i][j], aa, bb[j]);
                    mma_tf32(acc[i][j], aa, br[j]);
                    mma_tf32(acc[i][j], ar, bb[j]);
                }
            }
        }
        __syncthreads();
    }

    // normal tile write
#pragma unroll
    for (int i = 0; i < 4; i++) {
        int r = n0 + wm * 64 + i * 16 + g;
#pragma unroll
        for (int j = 0; j < 4; j++) {
            int cc = m0 + wn * 32 + j * 8 + 2 * t;
            *(float2*)&Lb[(size_t)r * HW + cc] =
                make_float2(acc[i][j][0], acc[i][j][1]);
            *(float2*)&Lb[(size_t)(r + 8) * HW + cc] =
                make_float2(acc[i][j][2], acc[i][j][3]);
        }
    }
    // mirrored tile (sector-aligned scattered stores: 8 lanes hit one 32B sector)
    if (SYM && bx != by) {
#pragma unroll
        for (int i = 0; i < 4; i++) {
            int rr = n0 + wm * 64 + i * 16 + g;
#pragma unroll
            for (int j = 0; j < 4; j++) {
                int cc = m0 + wn * 32 + j * 8 + 2 * t;
                Lb[(size_t)cc * HW + rr]           = acc[i][j][0];
                Lb[(size_t)(cc + 1) * HW + rr]     = acc[i][j][1];
                Lb[(size_t)cc * HW + rr + 8]       = acc[i][j][2];
                Lb[(size_t)(cc + 1) * HW + rr + 8] = acc[i][j][3];
            }
        }
    }
}

// =====================================================================
// gemm_rr: C[m][n] = sum_k A[m][k] * B[k][n]  (proven R3 kernel)
// =====================================================================
template<bool THREE, int EPI>
__global__ __launch_bounds__(256, 2)
void gemm_rr(const float* __restrict__ A, const float* __restrict__ B,
             const float* __restrict__ bias,
             const float* __restrict__ U, const float* __restrict__ Rr,
             float* __restrict__ C,
             int K, int lda, size_t sA, size_t sB, size_t sC) {
    extern __shared__ unsigned sm[];
    unsigned* As  = sm;
    unsigned* Asr = As + 128 * 36;
    unsigned* Bs  = As + (THREE ? 2 : 1) * 128 * 36;
    unsigned* Bsr = Bs + 32 * 136;

    int b = blockIdx.z;
    const float* Ab = A + (size_t)b * sA;
    const float* Bb = B + (size_t)b * sB;
    int n0 = blockIdx.x * 128;
    int m0 = blockIdx.y * 128;
    int tid = threadIdx.x;
    int warp = tid >> 5, lane = tid & 31;
    int g = lane >> 2, t = lane & 3;
    int wm = warp >> 2, wn = warp & 3;
    int la_n = tid >> 3, la_k = (tid & 7) * 4;
    int lb_k = tid >> 5, lb_n = (tid & 31) * 4;

    float acc[4][4][4] = {};

    for (int k0 = 0; k0 < K; k0 += 32) {
#pragma unroll
        for (int u = 0; u < 4; u++) {
            int n = la_n + u * 32;
            float4 v = *(const float4*)&Ab[(size_t)(m0 + n) * lda + k0 + la_k];
            unsigned h0 = f2tf(v.x), h1 = f2tf(v.y), h2 = f2tf(v.z), h3 = f2tf(v.w);
            unsigned* p = &As[n * 36 + la_k];
            p[0] = h0; p[1] = h1; p[2] = h2; p[3] = h3;
            if (THREE) {
                unsigned* q = &Asr[n * 36 + la_k];
                q[0] = f2tf(v.x - __uint_as_float(h0));
                q[1] = f2tf(v.y - __uint_as_float(h1));
                q[2] = f2tf(v.z - __uint_as_float(h2));
                q[3] = f2tf(v.w - __uint_as_float(h3));
            }
        }
#pragma unroll
        for (int u = 0; u < 4; u++) {
            int k = lb_k + u * 8;
            float4 v = *(const float4*)&Bb[(size_t)(k0 + k) * CDIM + n0 + lb_n];
            unsigned h0 = f2tf(v.x), h1 = f2tf(v.y), h2 = f2tf(v.z), h3 = f2tf(v.w);
            unsigned* p = &Bs[k * 136 + lb_n];
            p[0] = h0; p[1] = h1; p[2] = h2; p[3] = h3;
            if (THREE) {
                unsigned* q = &Bsr[k * 136 + lb_n];
                q[0] = f2tf(v.x - __uint_as_float(h0));
                q[1] = f2tf(v.y - __uint_as_float(h1));
                q[2] = f2tf(v.z - __uint_as_float(h2));
                q[3] = f2tf(v.w - __uint_as_float(h3));
            }
        }
        __syncthreads();

#pragma unroll
        for (int c = 0; c < 4; c++) {
            int kc = c * 8;
            unsigned bb[4][2], br[4][2];
#pragma unroll
            for (int j = 0; j < 4; j++) {
                int col = wn * 32 + j * 8 + g;
                bb[j][0] = Bs[(kc + t) * 136 + col];
                bb[j][1] = Bs[(kc + t + 4) * 136 + col];
                if (THREE) {
                    br[j][0] = Bsr[(kc + t) * 136 + col];
                    br[j][1] = Bsr[(kc + t + 4) * 136 + col];
                }
            }
#pragma unroll
            for (int i = 0; i < 4; i++) {
                int row = wm * 64 + i * 16 + g;
                unsigned aa[4], ar[4];
                aa[0] = As[row * 36 + kc + t];
                aa[1] = As[(row + 8) * 36 + kc + t];
                aa[2] = As[row * 36 + kc + t + 4];
                aa[3] = As[(row + 8) * 36 + kc + t + 4];
                if (THREE) {
                    ar[0] = Asr[row * 36 + kc + t];
                    ar[1] = Asr[(row + 8) * 36 + kc + t];
                    ar[2] = Asr[row * 36 + kc + t + 4];
                    ar[3] = Asr[(row + 8) * 36 + kc + t + 4];
                }
#pragma unroll
                for (int j = 0; j < 4; j++) {
                    mma_tf32(acc[i][j], aa, bb[j]);
                    if (THREE) {
                        mma_tf32(acc[i][j], aa, br[j]);
                        mma_tf32(acc[i][j], ar, bb[j]);
                    }
                }
            }
        }
        __syncthreads();
    }

    float* Cb = C + (size_t)b * sC;
#pragma unroll
    for (int i = 0; i < 4; i++) {
        int r = m0 + wm * 64 + i * 16 + g;
#pragma unroll
        for (int j = 0; j < 4; j++) {
            int cc = n0 + wn * 32 + j * 8 + 2 * t;
            size_t o0 = (size_t)r * CDIM + cc;
            size_t o1 = (size_t)(r + 8) * CDIM + cc;
            if (EPI == 1) {
                float2 bv = *(const float2*)&bias[cc];
                float2 v0 = make_float2(fmaxf(acc[i][j][0] + bv.x, 0.f),
                                        fmaxf(acc[i][j][1] + bv.y, 0.f));
                float2 v1 = make_float2(fmaxf(acc[i][j][2] + bv.x, 0.f),
                                        fmaxf(acc[i][j][3] + bv.y, 0.f));
                *(float2*)&Cb[o0] = v0;
                *(float2*)&Cb[o1] = v1;
            } else {
                const float* Ub = U + (size_t)b * sC;
                const float* Rb = Rr + (size_t)b * sC;
                float2 u0 = *(const float2*)&Ub[o0], u1 = *(const float2*)&Ub[o1];
                float2 q0 = *(const float2*)&Rb[o0], q1 = *(const float2*)&Rb[o1];
                float2 v0 = make_float2(acc[i][j][0] + u0.x + q0.x,
                                        acc[i][j][1] + u0.y + q0.y);
                float2 v1 = make_float2(acc[i][j][2] + u1.x + q1.x,
                                        acc[i][j][3] + u1.y + q1.y);
                *(float2*)&Cb[o0] = v0;
                *(float2*)&Cb[o1] = v1;
            }
        }
    }
}

// ---------------- row softmax in place ----------------
__global__ void softmax_kernel(float* __restrict__ P) {
    float* row = P + ((size_t)blockIdx.y * HW + blockIdx.x) * HW;
    int t = threadIdx.x;
    __shared__ float red[16];
    float v[8];
    float mx = -1e30f;
#pragma unroll
    for (int i = 0; i < 8; i++) { v[i] = row[t + i * 512]; mx = fmaxf(mx, v[i]); }
    for (int o = 16; o; o >>= 1) mx = fmaxf(mx, __shfl_xor_sync(0xffffffffu, mx, o));
    int warp = t >> 5, lane = t & 31;
    if (lane == 0) red[warp] = mx;
    __syncthreads();
    if (warp == 0) {
        float m2 = red[lane & 15];
        for (int o = 8; o; o >>= 1) m2 = fmaxf(m2, __shfl_xor_sync(0xffffffffu, m2, o));
        if (lane == 0) red[0] = m2;
    }
    __syncthreads();
    mx = red[0];
    __syncthreads();
    float s = 0.f;
#pragma unroll
    for (int i = 0; i < 8; i++) { v[i] = __expf(v[i] - mx); s += v[i]; }
    for (int o = 16; o; o >>= 1) s += __shfl_xor_sync(0xffffffffu, s, o);
    if (lane == 0) red[warp] = s;
    __syncthreads();
    if (warp == 0) {
        float s2 = red[lane & 15];
        for (int o = 8; o; o >>= 1) s2 += __shfl_xor_sync(0xffffffffu, s2, o);
        if (lane == 0) red[0] = s2;
    }
    __syncthreads();
    float inv = 1.f / red[0];
#pragma unroll
    for (int i = 0; i < 8; i++) row[t + i * 512] = v[i] * inv;
}

// ---------------- column partial sums ----------------
__global__ void colsum_kernel(const float* __restrict__ P, float* __restrict__ part) {
    int b = blockIdx.z;
    int m = blockIdx.x * 256 + threadIdx.x;
    int r0 = blockIdx.y * 256;
    const float* Pb = P + (size_t)b * HW * HW;
    float s = 0.f;
#pragma unroll 8
    for (int r = 0; r < 256; r++) s += Pb[(size_t)(r0 + r) * HW + m];
    part[((size_t)b * 16 + blockIdx.y) * HW + m] = s;
}

__global__ void colinv_kernel(const float* __restrict__ part, float* __restrict__ colinv) {
    int i = blockIdx.x * 256 + threadIdx.x;
    int b = i >> 12, m = i & (HW - 1);
    float s = 0.f;
#pragma unroll
    for (int c2 = 0; c2 < 16; c2++) s += part[((size_t)b * 16 + c2) * HW + m];
    colinv[i] = 1.f / fmaxf(s, 1e-12f);
}

__global__ void scale_ax_kernel(float* __restrict__ ax, const float* __restrict__ colinv) {
    size_t f4 = (size_t)blockIdx.x * 256 + threadIdx.x;
    int row = (int)(f4 >> 6);
    float sc = colinv[row];
    float4 v = ((float4*)ax)[f4];
    v.x *= sc; v.y *= sc; v.z *= sc; v.w *= sc;
    ((float4*)ax)[f4] = v;
}

// ---------------- launch ----------------
extern "C" void kernel_launch(void* const* d_in, const int* in_sizes, int n_in,
                              void* d_out, int out_size) {
    (void)in_sizes; (void)n_in; (void)out_size;
    const float* skt = (const float*)d_in[0];
    const float* ref = (const float*)d_in[1];
    const float* Wa3 = (const float*)d_in[2];
    const float* ba3 = (const float*)d_in[3];
    const float* Wu3 = (const float*)d_in[4];
    const float* bu3 = (const float*)d_in[5];
    const float* Wa4 = (const float*)d_in[6];
    const float* ba4 = (const float*)d_in[7];
    const float* Wu4 = (const float*)d_in[8];
    const float* bu4 = (const float*)d_in[9];
    float* out = (float*)d_out;

    float *P, *ax, *ux, *gen, *gencn, *sktnc, *refnc, *colpart, *colinv;
    unsigned *hi0, *lo0, *hi1, *lo1;
    cudaGetSymbolAddress((void**)&P, g_P);
    cudaGetSymbolAddress((void**)&ax, g_ax);
    cudaGetSymbolAddress((void**)&ux, g_ux);
    cudaGetSymbolAddress((void**)&gen, g_gen);
    cudaGetSymbolAddress((void**)&gencn, g_gencn);
    cudaGetSymbolAddress((void**)&sktnc, g_sktnc);
    cudaGetSymbolAddress((void**)&refnc, g_refnc);
    cudaGetSymbolAddress((void**)&colpart, g_colpart);
    cudaGetSymbolAddress((void**)&colinv, g_colinv);
    cudaGetSymbolAddress((void**)&hi0, g_hi0);
    cudaGetSymbolAddress((void**)&lo0, g_lo0);
    cudaGetSymbolAddress((void**)&hi1, g_hi1);
    cudaGetSymbolAddress((void**)&lo1, g_lo1);

    const int SM3  = (2 * 128 * 36 + 2 * 32 * 136) * 4;   // 71680
    const int SM1  = (128 * 36 + 32 * 136) * 4;           // 35840
    const int SMLC = 2 * 4 * 32 * 136 * 4;                // 139264
    cudaFuncSetAttribute(gemm_rr<true, 1>,  cudaFuncAttributeMaxDynamicSharedMemorySize, SM3);
    cudaFuncSetAttribute(gemm_rr<true, 2>,  cudaFuncAttributeMaxDynamicSharedMemorySize, SM3);
    cudaFuncSetAttribute(gemm_rr<false, 1>, cudaFuncAttributeMaxDynamicSharedMemorySize, SM1);
    cudaFuncSetAttribute(gemm_rr<false, 2>, cudaFuncAttributeMaxDynamicSharedMemorySize, SM1);
    cudaFuncSetAttribute(logits_cp<false>,  cudaFuncAttributeMaxDynamicSharedMemorySize, SMLC);
    cudaFuncSetAttribute(logits_cp<true>,   cudaFuncAttributeMaxDynamicSharedMemorySize, SMLC);

    dim3 tb(32, 8);
    dim3 gLin(CDIM / 128, (BATCH * HW) / 128, 1);
    dim3 gLog(HW / 128, HW / 128, BATCH);
    dim3 gPax(CDIM / 128, HW / 128, BATCH);
    const int nSplit = (BATCH * HW * CDIM) / (4 * 256);

    // ===== layer 1 =====
    transpose_kernel<<<dim3(HW / 32, CDIM / 32, BATCH), tb>>>(skt, sktnc, CDIM, HW);
    transpose_kernel<<<dim3(HW / 32, CDIM / 32, BATCH), tb>>>(ref, refnc, CDIM, HW);
    split_kernel<<<nSplit, 256>>>(skt, hi0, lo0);
    split_kernel<<<nSplit, 256>>>(ref, hi1, lo1);
    gemm_rr<true, 1><<<gLin, 256, SM3>>>(refnc, Wa3, ba3, nullptr, nullptr, ax,
                                         CDIM, CDIM, 0, 0, 0);
    gemm_rr<true, 1><<<gLin, 256, SM3>>>(sktnc, Wu3, bu3, nullptr, nullptr, ux,
                                         CDIM, CDIM, 0, 0, 0);
    logits_cp<false><<<gLog, 256, SMLC>>>(hi0, lo0, hi1, lo1, P);
    softmax_kernel<<<dim3(HW, BATCH), 512>>>(P);
    colsum_kernel<<<dim3(HW / 256, 16, BATCH), 256>>>(P, colpart);
    colinv_kernel<<<(BATCH * HW) / 256, 256>>>(colpart, colinv);
    scale_ax_kernel<<<(BATCH * HW * CDIM) / (4 * 256), 256>>>(ax, colinv);
    gemm_rr<true, 2><<<gPax, 256, SM3>>>(P, ax, nullptr, ux, sktnc, gen,
                                         HW, HW,
                                         (size_t)HW * HW, (size_t)HW * CDIM, (size_t)HW * CDIM);

    // ===== layer 2 (logits symmetric: gen.genT) =====
    transpose_kernel<<<dim3(CDIM / 32, HW / 32, BATCH), tb>>>(gen, gencn, HW, CDIM);
    split_kernel<<<nSplit, 256>>>(gencn, hi0, lo0);
    gemm_rr<false, 1><<<gLin, 256, SM1>>>(gen, Wa4, ba4, nullptr, nullptr, ax,
                                          CDIM, CDIM, 0, 0, 0);
    gemm_rr<false, 1><<<gLin, 256, SM1>>>(gen, Wu4, bu4, nullptr, nullptr, ux,
                                          CDIM, CDIM, 0, 0, 0);
    logits_cp<true><<<gLog, 256, SMLC>>>(hi0, lo0, hi0, lo0, P);
    softmax_kernel<<<dim3(HW, BATCH), 512>>>(P);
    colsum_kernel<<<dim3(HW / 256, 16, BATCH), 256>>>(P, colpart);
    colinv_kernel<<<(BATCH * HW) / 256, 256>>>(colpart, colinv);
    scale_ax_kernel<<<(BATCH * HW * CDIM) / (4 * 256), 256>>>(ax, colinv);
    gemm_rr<false, 2><<<gPax, 256, SM1>>>(P, ax, nullptr, ux, gen, out,
                                          HW, HW,
                                          (size_t)HW * HW, (size_t)HW * CDIM, (size_t)HW * CDIM);
}